// round 12
// baseline (speedup 1.0000x reference)
#include <cuda_runtime.h>
#include <cstdint>

#define IN 784
#define HIDN 64
#define KTOP 20
#define KCH_E 98              // 98 chunks of 8 k (784 = 98*8)
#define KCH_D 8               // decoder k-chunks
#define NPAD 832
#define EPS_GAP 1e-4f

// Pre-split weights. Layout [kc][n][k*2+hl]: one thread's 4 B-scalars per mma
// tile = one float4 = (bh(2tg), bl(2tg), bh(2tg+1), bl(2tg+1)).
__device__ float g_Be[KCH_E * 64 * 16];       // 100352 floats
__device__ float g_Bd[KCH_D * NPAD * 16];     // 106496 floats

// ---- tf32 helpers ----
__device__ __forceinline__ unsigned tf32r(float v) {
    unsigned r; asm("cvt.rna.tf32.f32 %0, %1;" : "=r"(r) : "f"(v)); return r;
}
// Fast split: tf32 HMMA reads only bits[31:13]; hi = mask, lo = raw residual.
__device__ __forceinline__ void splitm(float v, unsigned &hi, unsigned &lo) {
    unsigned b = __float_as_uint(v);
    hi = b & 0xFFFFE000u;
    lo = __float_as_uint(v - __uint_as_float(hi));
}
__device__ __forceinline__ void mma8(float* c, const unsigned* a, unsigned b0, unsigned b1) {
    asm volatile(
        "mma.sync.aligned.m16n8k8.row.col.f32.tf32.tf32.f32 "
        "{%0,%1,%2,%3},{%4,%5,%6,%7},{%8,%9},{%0,%1,%2,%3};"
        : "+f"(c[0]), "+f"(c[1]), "+f"(c[2]), "+f"(c[3])
        : "r"(a[0]), "r"(a[1]), "r"(a[2]), "r"(a[3]), "r"(b0), "r"(b1));
}
__device__ __forceinline__ void mma3(float* c, const unsigned* ah, const unsigned* al, float4 bv) {
    unsigned bh0 = __float_as_uint(bv.x), bl0 = __float_as_uint(bv.y);
    unsigned bh1 = __float_as_uint(bv.z), bl1 = __float_as_uint(bv.w);
    mma8(c, ah, bh0, bh1);
    mma8(c, al, bh0, bh1);
    mma8(c, ah, bl0, bl1);
}
// ---- cp.async ----
__device__ __forceinline__ void cp16(void* sdst, const void* gsrc) {
    unsigned sa = (unsigned)__cvta_generic_to_shared(sdst);
    asm volatile("cp.async.ca.shared.global [%0], [%1], 16;" :: "r"(sa), "l"(gsrc));
}
#define CP_COMMIT() asm volatile("cp.async.commit_group;")
#define CP_WAIT4()  asm volatile("cp.async.wait_group 4;" ::: "memory")
#define CP_WAIT0()  asm volatile("cp.async.wait_group 0;" ::: "memory")

// ---------------- K0: split + rearrange weights ----------------
__global__ void k_prep(const float* __restrict__ We, const float* __restrict__ Wd) {
    int idx = blockIdx.x * 256 + threadIdx.x;
    const int NE = KCH_E * 1024;
    if (idx < NE) {
        int kc = idx >> 10, r = idx & 1023;
        int n = r >> 4, q = r & 15, kk = q >> 1, hl = q & 1;
        float w = We[n * IN + kc * 8 + kk];
        unsigned h = tf32r(w);
        g_Be[idx] = hl ? __uint_as_float(tf32r(w - __uint_as_float(h)))
                       : __uint_as_float(h);
    }
    int j = idx - NE;
    const int ND = KCH_D * NPAD * 16;
    if (j >= 0 && j < ND) {
        int kc = j / (NPAD * 16);
        int r  = j % (NPAD * 16);
        int n = r >> 4, q = r & 15, kk = q >> 1, hl = q & 1;
        float w = (n < IN) ? Wd[n * HIDN + kc * 8 + kk] : 0.f;
        unsigned h = tf32r(w);
        g_Bd[j] = hl ? __uint_as_float(tf32r(w - __uint_as_float(h)))
                     : __uint_as_float(h);
    }
}

// ---------------- K1: fused encoder GEMM (3xTF32) + bias + ReLU + top-k -----
// CTA = 256 rows x 64 cols, 8 warps, warp = 32 rows (two A frags).
// 8-stage cp.async pipeline, 2 chunks (16 k) per barrier. Unconditional
// commit groups keep the wait_group arithmetic exact through the tail.
// Epilogue: acc -> smem h-tile -> warp-per-row top-21 -> gated write to hout,
// with inline exact fp32 repair for fragile rows.
// Dyn smem: xs 8 stages x 8KB @0, ws 8 stages x 4KB @65536; h-tile reuses @0.
__global__ __launch_bounds__(256, 2) void k_enc(const float* __restrict__ x,
        const float* __restrict__ We, const float* __restrict__ benc,
        float* __restrict__ hout, int B) {
    extern __shared__ char dyn[];
    const int tid = threadIdx.x, lane = tid & 31, w = tid >> 5;
    const int g = lane >> 2, tg = lane & 3;
    const int r0 = blockIdx.x * 256;
    const long xrow = (long)min(r0 + tid, B - 1) * IN;
    const int mr = w * 32;

    float acc[8][8];
    #pragma unroll
    for (int t = 0; t < 8; t++)
        #pragma unroll
        for (int i = 0; i < 8; i++) acc[t][i] = 0.f;

    // prologue: chunks 0..5 (6 commit groups)
    #pragma unroll
    for (int kc = 0; kc < 6; kc++) {
        int s = kc & 7;
        cp16(dyn + 65536 + s * 4096 + tid * 16, g_Be + kc * 1024 + tid * 4);
        cp16(dyn + s * 8192 + tid * 32,      x + xrow + kc * 8);
        cp16(dyn + s * 8192 + tid * 32 + 16, x + xrow + kc * 8 + 4);
        CP_COMMIT();
    }

    for (int it = 0; it < 49; it++) {
        CP_WAIT4();                 // chunks <= 2it+1 landed (see commit math)
        __syncthreads();

        // issue chunks 2it+6, 2it+7 (or empty groups to keep counting exact)
        #pragma unroll
        for (int u = 0; u < 2; u++) {
            int kc = 2 * it + 6 + u;
            if (kc < KCH_E) {
                int s = kc & 7;
                cp16(dyn + 65536 + s * 4096 + tid * 16, g_Be + kc * 1024 + tid * 4);
                cp16(dyn + s * 8192 + tid * 32,      x + xrow + kc * 8);
                cp16(dyn + s * 8192 + tid * 32 + 16, x + xrow + kc * 8 + 4);
            }
            CP_COMMIT();
        }

        // compute chunks 2it, 2it+1
        #pragma unroll
        for (int u = 0; u < 2; u++) {
            int kc = 2 * it + u, s = kc & 7;
            const float* xsp = (const float*)(dyn + s * 8192);
            const float* wsp = (const float*)(dyn + 65536 + s * 4096);
            float2 a0 = *(const float2*)(xsp + (mr + g     ) * 8 + 2 * tg);
            float2 a1 = *(const float2*)(xsp + (mr + g +  8) * 8 + 2 * tg);
            float2 a2 = *(const float2*)(xsp + (mr + g + 16) * 8 + 2 * tg);
            float2 a3 = *(const float2*)(xsp + (mr + g + 24) * 8 + 2 * tg);
            unsigned ah0[4], al0[4], ah1[4], al1[4];
            splitm(a0.x, ah0[0], al0[0]); splitm(a1.x, ah0[1], al0[1]);
            splitm(a0.y, ah0[2], al0[2]); splitm(a1.y, ah0[3], al0[3]);
            splitm(a2.x, ah1[0], al1[0]); splitm(a3.x, ah1[1], al1[1]);
            splitm(a2.y, ah1[2], al1[2]); splitm(a3.y, ah1[3], al1[3]);
            #pragma unroll
            for (int t = 0; t < 8; t++) {
                float4 bv = *(const float4*)(wsp + (t * 8 + g) * 16 + 4 * tg);
                mma3(acc[t],     ah0, al0, bv);
                mma3(acc[t] + 4, ah1, al1, bv);
            }
        }
    }

    // ---- epilogue: bias + ReLU into smem h-tile ----
    __syncthreads();                       // all stages consumed; reuse smem
    float* ht = (float*)dyn;               // [256][64]
    #pragma unroll
    for (int t = 0; t < 8; t++) {
        int col = t * 8 + 2 * tg;
        float2 bb = *(const float2*)(benc + col);
        #pragma unroll
        for (int s = 0; s < 4; s++) {
            int lr = mr + g + 8 * s;
            float u0 = (s & 1) ? acc[t][(s >> 1) * 4 + 2] : acc[t][(s >> 1) * 4 + 0];
            float u1 = (s & 1) ? acc[t][(s >> 1) * 4 + 3] : acc[t][(s >> 1) * 4 + 1];
            float2 o = make_float2(fmaxf(u0 + bb.x, 0.f), fmaxf(u1 + bb.y, 0.f));
            *(float2*)(ht + lr * 64 + col) = o;
        }
    }
    __syncthreads();

    // ---- top-20 gating, warp-per-row (32 rows per warp) ----
    for (int r = 0; r < 32; r++) {
        int row = r0 + mr + r;
        if (row >= B) break;
        float v0 = ht[(mr + r) * 64 + lane];
        float v1 = ht[(mr + r) * 64 + lane + 32];
        float* hr = hout + (size_t)row * HIDN;

        unsigned q0 = (__float_as_uint(v0) & ~63u) | (unsigned)(63 - lane);
        unsigned q1 = (__float_as_uint(v1) & ~63u) | (unsigned)(31 - lane);
        float thr = 0.f, nxt = 0.f;
        #pragma unroll
        for (int itk = 0; itk < KTOP + 1; itk++) {
            unsigned m = (q0 > q1) ? q0 : q1;
            #pragma unroll
            for (int off = 16; off > 0; off >>= 1) {
                unsigned o = __shfl_xor_sync(0xffffffffu, m, off);
                if (o > m) m = o;
            }
            if (itk == KTOP - 1) thr = __uint_as_float(m & ~63u);
            if (itk == KTOP)     nxt = __uint_as_float(m & ~63u);
            if (q0 == m) q0 = 0u; else if (q1 == m) q1 = 0u;
        }

        if (thr - nxt >= EPS_GAP) {
            hr[lane]      = (v0 >= thr) ? v0 : 0.f;
            hr[lane + 32] = (v1 >= thr) ? v1 : 0.f;
            continue;
        }

        // Fragile: exact fp32 recompute + exact 64-bit-key top-k.
        const float* xr = x + (size_t)row * IN;
        const float* wa = We + (size_t)lane * IN;
        const float* wb = We + (size_t)(lane + 32) * IN;
        float a0 = 0.f, a1 = 0.f;
        for (int k = 0; k < IN; k += 4) {
            float4 xv = *(const float4*)(xr + k);
            float4 va = *(const float4*)(wa + k);
            float4 vb = *(const float4*)(wb + k);
            a0 += xv.x*va.x + xv.y*va.y + xv.z*va.z + xv.w*va.w;
            a1 += xv.x*vb.x + xv.y*vb.y + xv.z*vb.z + xv.w*vb.w;
        }
        v0 = fmaxf(a0 + benc[lane], 0.f);
        v1 = fmaxf(a1 + benc[lane + 32], 0.f);
        unsigned long long k0 = ((unsigned long long)__float_as_uint(v0) << 32) | (unsigned)(63 - lane);
        unsigned long long k1 = ((unsigned long long)__float_as_uint(v1) << 32) | (unsigned)(31 - lane);
        float thx = 0.f;
        #pragma unroll
        for (int itk = 0; itk < KTOP; itk++) {
            unsigned long long m = (k0 > k1) ? k0 : k1;
            #pragma unroll
            for (int off = 16; off > 0; off >>= 1) {
                unsigned long long o = __shfl_xor_sync(0xffffffffu, m, off);
                if (o > m) m = o;
            }
            if (itk == KTOP - 1) thx = __uint_as_float((unsigned)(m >> 32));
            if (k0 == m) k0 = 0ull; else if (k1 == m) k1 = 0ull;
        }
        hr[lane]      = (v0 >= thx) ? v0 : 0.f;
        hr[lane + 32] = (v1 >= thx) ? v1 : 0.f;
    }
}

// ---------------- K3: decoder GEMM (3xTF32, mma.sync) + bias ----------------
__global__ __launch_bounds__(256, 2) void k_dec(const float* __restrict__ h,
        const float* __restrict__ bdec, float* __restrict__ xhat, int B) {
    __shared__ float ws[KCH_D][64][16];
    const int tid = threadIdx.x, lane = tid & 31, w = tid >> 5;
    const int g = lane >> 2, tg = lane & 3;
    const int r0 = blockIdx.x * 256;
    const int n0 = blockIdx.y * 64;
    const int rowb = r0 + w * 32 + g;
    const float* hp[4];
    #pragma unroll
    for (int j = 0; j < 4; j++) {
        int r = min(rowb + 8 * j, B - 1);
        hp[j] = h + (size_t)r * HIDN + 2 * tg;
    }

    #pragma unroll
    for (int i = 0; i < 8; i++) {
        int f = tid + i * 256;
        int kc = f >> 8, q = f & 255, n = q >> 2, part = q & 3;
        cp16(&ws[kc][n][part * 4],
             g_Bd + ((size_t)kc * NPAD + n0 + n) * 16 + part * 4);
    }
    CP_COMMIT();
    CP_WAIT0();
    __syncthreads();

    float acc[8][8];
    #pragma unroll
    for (int t = 0; t < 8; t++)
        #pragma unroll
        for (int i = 0; i < 8; i++) acc[t][i] = 0.f;

    #pragma unroll
    for (int kc = 0; kc < KCH_D; kc++) {
        float2 a0 = *(const float2*)(hp[0] + kc * 8);
        float2 a1 = *(const float2*)(hp[1] + kc * 8);
        float2 a2 = *(const float2*)(hp[2] + kc * 8);
        float2 a3 = *(const float2*)(hp[3] + kc * 8);
        unsigned ah0[4], al0[4], ah1[4], al1[4];
        splitm(a0.x, ah0[0], al0[0]); splitm(a1.x, ah0[1], al0[1]);
        splitm(a0.y, ah0[2], al0[2]); splitm(a1.y, ah0[3], al0[3]);
        splitm(a2.x, ah1[0], al1[0]); splitm(a3.x, ah1[1], al1[1]);
        splitm(a2.y, ah1[2], al1[2]); splitm(a3.y, ah1[3], al1[3]);
        #pragma unroll
        for (int t = 0; t < 8; t++) {
            float4 bv = *(const float4*)&ws[kc][t * 8 + g][4 * tg];
            mma3(acc[t],     ah0, al0, bv);
            mma3(acc[t] + 4, ah1, al1, bv);
        }
    }

    #pragma unroll
    for (int t = 0; t < 8; t++) {
        int col = n0 + t * 8 + 2 * tg;
        if (col < IN) {
            float2 bb = *(const float2*)(bdec + col);
            #pragma unroll
            for (int s = 0; s < 4; s++) {
                int r = rowb + 8 * s;
                if (r < B) {
                    float u0 = (s & 1) ? acc[t][(s >> 1) * 4 + 2] : acc[t][(s >> 1) * 4 + 0];
                    float u1 = (s & 1) ? acc[t][(s >> 1) * 4 + 3] : acc[t][(s >> 1) * 4 + 1];
                    float2 o = make_float2(u0 + bb.x, u1 + bb.y);
                    *(float2*)(xhat + (size_t)r * IN + col) = o;
                }
            }
        }
    }
}

extern "C" void kernel_launch(void* const* d_in, const int* in_sizes, int n_in,
                              void* d_out, int out_size) {
    const float* x    = (const float*)d_in[0];
    const float* We   = (const float*)d_in[1];
    const float* benc = (const float*)d_in[2];
    const float* Wd   = (const float*)d_in[3];
    const float* bdec = (const float*)d_in[4];
    int B = in_sizes[0] / IN;

    float* hout = (float*)d_out;                         // [B, 64]
    float* xhat = (float*)d_out + (size_t)B * HIDN;      // [B, 784]

    const int SMEM_ENC = 8 * 8192 + 8 * 4096;            // 98304 bytes
    cudaFuncSetAttribute(k_enc, cudaFuncAttributeMaxDynamicSharedMemorySize, SMEM_ENC);

    const int NPREP = KCH_E * 1024 + KCH_D * NPAD * 16;
    k_prep<<<(NPREP + 255) / 256, 256>>>(We, Wd);
    k_enc<<<(B + 255) / 256, 256, SMEM_ENC>>>(x, We, benc, hout, B);
    k_dec<<<dim3((B + 255) / 256, 13), 256>>>(hout, bdec, xhat, B);
}

// round 13
// speedup vs baseline: 1.1295x; 1.1295x over previous
#include <cuda_runtime.h>
#include <cstdint>

#define IN 784
#define HIDN 64
#define KTOP 20
#define KCH_E 98              // 98 chunks of 8 k (784 = 98*8)
#define KCH_D 8               // decoder k-chunks
#define NPAD 832
#define EPS_GAP 1e-4f
#define NSTG 49               // encoder stage-pairs (2 chunks each)

// Pre-split weights. Layout [kc][n][k*2+hl]: one thread's 4 B-scalars per mma
// tile = one float4 = (bh(2tg), bl(2tg), bh(2tg+1), bl(2tg+1)).
__device__ float g_Be[KCH_E * 1024];          // 100352 floats
__device__ float g_Bd[KCH_D * NPAD * 16];     // 106496 floats

// ---- tf32 helpers ----
__device__ __forceinline__ unsigned tf32r(float v) {
    unsigned r; asm("cvt.rna.tf32.f32 %0, %1;" : "=r"(r) : "f"(v)); return r;
}
// Fast split: tf32 HMMA reads only bits[31:13]; hi = mask, lo = raw residual.
__device__ __forceinline__ void splitm(float v, unsigned &hi, unsigned &lo) {
    unsigned b = __float_as_uint(v);
    hi = b & 0xFFFFE000u;
    lo = __float_as_uint(v - __uint_as_float(hi));
}
__device__ __forceinline__ void mma8(float* c, const unsigned* a, unsigned b0, unsigned b1) {
    asm volatile(
        "mma.sync.aligned.m16n8k8.row.col.f32.tf32.tf32.f32 "
        "{%0,%1,%2,%3},{%4,%5,%6,%7},{%8,%9},{%0,%1,%2,%3};"
        : "+f"(c[0]), "+f"(c[1]), "+f"(c[2]), "+f"(c[3])
        : "r"(a[0]), "r"(a[1]), "r"(a[2]), "r"(a[3]), "r"(b0), "r"(b1));
}
__device__ __forceinline__ void mma3(float* c, const unsigned* ah, const unsigned* al, float4 bv) {
    unsigned bh0 = __float_as_uint(bv.x), bl0 = __float_as_uint(bv.y);
    unsigned bh1 = __float_as_uint(bv.z), bl1 = __float_as_uint(bv.w);
    mma8(c, ah, bh0, bh1);
    mma8(c, al, bh0, bh1);
    mma8(c, ah, bl0, bl1);
}
// ---- cp.async ----
__device__ __forceinline__ void cp16(void* sdst, const void* gsrc) {
    unsigned sa = (unsigned)__cvta_generic_to_shared(sdst);
    asm volatile("cp.async.ca.shared.global [%0], [%1], 16;" :: "r"(sa), "l"(gsrc));
}
#define CP_COMMIT() asm volatile("cp.async.commit_group;")
#define CP_WAIT2()  asm volatile("cp.async.wait_group 2;" ::: "memory")
#define CP_WAIT0()  asm volatile("cp.async.wait_group 0;" ::: "memory")

// ---------------- K0: split + rearrange weights ----------------
__global__ void k_prep(const float* __restrict__ We, const float* __restrict__ Wd) {
    int idx = blockIdx.x * 256 + threadIdx.x;
    const int NE = KCH_E * 1024;
    if (idx < NE) {
        int kc = idx >> 10, r = idx & 1023;
        int n = r >> 4, q = r & 15, kk = q >> 1, hl = q & 1;
        float w = We[n * IN + kc * 8 + kk];
        unsigned h = tf32r(w);
        g_Be[idx] = hl ? __uint_as_float(tf32r(w - __uint_as_float(h)))
                       : __uint_as_float(h);
    }
    int j = idx - NE;
    const int ND = KCH_D * NPAD * 16;
    if (j >= 0 && j < ND) {
        int kc = j / (NPAD * 16);
        int r  = j % (NPAD * 16);
        int n = r >> 4, q = r & 15, kk = q >> 1, hl = q & 1;
        float w = (n < IN) ? Wd[n * HIDN + kc * 8 + kk] : 0.f;
        unsigned h = tf32r(w);
        g_Bd[j] = hl ? __uint_as_float(tf32r(w - __uint_as_float(h)))
                     : __uint_as_float(h);
    }
}

// ---------------- K1: encoder GEMM (3xTF32) + bias + ReLU ----------------
// CTA = 256 rows x 64 cols, 8 warps, warp = 32 rows (two A frags).
// 4 stage-pairs x 2 chunks (16 k) per barrier: 49 barrier drains instead of 98.
// Stage layout (24576 B): xsA[256][8] | xsB[256][8] | wsA[64][16] | wsB[64][16]
// -- byte-identical access patterns to the proven R10 single-chunk stages.
__global__ __launch_bounds__(256, 2) void k_enc(const float* __restrict__ x,
        const float* __restrict__ benc, float* __restrict__ hout, int B) {
    extern __shared__ char dyn[];
    const int tid = threadIdx.x, lane = tid & 31, w = tid >> 5;
    const int g = lane >> 2, tg = lane & 3;
    const int r0 = blockIdx.x * 256;
    const long xrow = (long)min(r0 + tid, B - 1) * IN;
    const int mr = w * 32;

    float acc[8][8];
    #pragma unroll
    for (int t = 0; t < 8; t++)
        #pragma unroll
        for (int i = 0; i < 8; i++) acc[t][i] = 0.f;

    // prologue: stage-pairs 0..2 (chunks 0..5), one commit per stage-pair
    #pragma unroll
    for (int s = 0; s < 3; s++) {
        char* sb = dyn + s * 24576;
        int kc = 2 * s;
        cp16(sb + tid * 32,              x + xrow + kc * 8);
        cp16(sb + tid * 32 + 16,         x + xrow + kc * 8 + 4);
        cp16(sb + 8192 + tid * 32,       x + xrow + (kc + 1) * 8);
        cp16(sb + 8192 + tid * 32 + 16,  x + xrow + (kc + 1) * 8 + 4);
        cp16(sb + 16384 + tid * 16,      g_Be + kc * 1024 + tid * 4);
        cp16(sb + 20480 + tid * 16,      g_Be + (kc + 1) * 1024 + tid * 4);
        CP_COMMIT();
    }

    for (int it = 0; it < NSTG; it++) {
        CP_WAIT2();                 // stage-pairs <= it landed
        __syncthreads();

        // issue stage-pair it+3 (slot of pair it-1, computed last iteration);
        // unconditional commit keeps the wait_group count exact in the tail
        {
            int sp = it + 3;
            if (sp < NSTG) {
                char* sb = dyn + (sp & 3) * 24576;
                int kc = 2 * sp;
                cp16(sb + tid * 32,              x + xrow + kc * 8);
                cp16(sb + tid * 32 + 16,         x + xrow + kc * 8 + 4);
                cp16(sb + 8192 + tid * 32,       x + xrow + (kc + 1) * 8);
                cp16(sb + 8192 + tid * 32 + 16,  x + xrow + (kc + 1) * 8 + 4);
                cp16(sb + 16384 + tid * 16,      g_Be + kc * 1024 + tid * 4);
                cp16(sb + 20480 + tid * 16,      g_Be + (kc + 1) * 1024 + tid * 4);
            }
            CP_COMMIT();
        }

        // compute the two chunks of stage-pair it
        const char* sb = dyn + (it & 3) * 24576;
        #pragma unroll
        for (int u = 0; u < 2; u++) {
            const float* xsp = (const float*)(sb + u * 8192);
            const float* wsp = (const float*)(sb + 16384 + u * 4096);
            float2 a0 = *(const float2*)(xsp + (mr + g     ) * 8 + 2 * tg);
            float2 a1 = *(const float2*)(xsp + (mr + g +  8) * 8 + 2 * tg);
            float2 a2 = *(const float2*)(xsp + (mr + g + 16) * 8 + 2 * tg);
            float2 a3 = *(const float2*)(xsp + (mr + g + 24) * 8 + 2 * tg);
            unsigned ah0[4], al0[4], ah1[4], al1[4];
            splitm(a0.x, ah0[0], al0[0]); splitm(a1.x, ah0[1], al0[1]);
            splitm(a0.y, ah0[2], al0[2]); splitm(a1.y, ah0[3], al0[3]);
            splitm(a2.x, ah1[0], al1[0]); splitm(a3.x, ah1[1], al1[1]);
            splitm(a2.y, ah1[2], al1[2]); splitm(a3.y, ah1[3], al1[3]);
            #pragma unroll
            for (int t = 0; t < 8; t++) {
                float4 bv = *(const float4*)(wsp + (t * 8 + g) * 16 + 4 * tg);
                mma3(acc[t],     ah0, al0, bv);
                mma3(acc[t] + 4, ah1, al1, bv);
            }
        }
    }

    const int rowb = r0 + mr + g;
    #pragma unroll
    for (int t = 0; t < 8; t++) {
        int col = t * 8 + 2 * tg;
        float2 bb = *(const float2*)(benc + col);
        #pragma unroll
        for (int s = 0; s < 4; s++) {
            int r = rowb + 8 * s;
            if (r < B) {
                float u0 = (s & 1) ? acc[t][(s >> 1) * 4 + 2] : acc[t][(s >> 1) * 4 + 0];
                float u1 = (s & 1) ? acc[t][(s >> 1) * 4 + 3] : acc[t][(s >> 1) * 4 + 1];
                float2 o = make_float2(fmaxf(u0 + bb.x, 0.f), fmaxf(u1 + bb.y, 0.f));
                *(float2*)(hout + (size_t)r * HIDN + col) = o;
            }
        }
    }
}

// ---------------- K2: top-20 gating (32-bit keys) + inline exact repair -----
__global__ __launch_bounds__(256) void k_topk(const float* __restrict__ x,
        const float* __restrict__ We, const float* __restrict__ benc,
        float* __restrict__ h, int B) {
    int warp = threadIdx.x >> 5, lane = threadIdx.x & 31;
    int row = blockIdx.x * 8 + warp;
    if (row >= B) return;
    float* hr = h + (size_t)row * HIDN;
    float v0 = hr[lane], v1 = hr[lane + 32];

    unsigned q0 = (__float_as_uint(v0) & ~63u) | (unsigned)(63 - lane);
    unsigned q1 = (__float_as_uint(v1) & ~63u) | (unsigned)(31 - lane);
    float thr = 0.f, nxt = 0.f;
    #pragma unroll
    for (int it = 0; it < KTOP + 1; it++) {
        unsigned m = (q0 > q1) ? q0 : q1;
        #pragma unroll
        for (int off = 16; off > 0; off >>= 1) {
            unsigned o = __shfl_xor_sync(0xffffffffu, m, off);
            if (o > m) m = o;
        }
        if (it == KTOP - 1) thr = __uint_as_float(m & ~63u);
        if (it == KTOP)     nxt = __uint_as_float(m & ~63u);
        if (q0 == m) q0 = 0u; else if (q1 == m) q1 = 0u;
    }

    if (thr - nxt >= EPS_GAP) {
        hr[lane]      = (v0 >= thr) ? v0 : 0.f;
        hr[lane + 32] = (v1 >= thr) ? v1 : 0.f;
        return;
    }

    // Fragile: exact fp32 recompute + exact 64-bit-key top-k.
    const float* xr = x + (size_t)row * IN;
    const float* wa = We + (size_t)lane * IN;
    const float* wb = We + (size_t)(lane + 32) * IN;
    float a0 = 0.f, a1 = 0.f;
    for (int k = 0; k < IN; k += 4) {
        float4 xv = *(const float4*)(xr + k);
        float4 va = *(const float4*)(wa + k);
        float4 vb = *(const float4*)(wb + k);
        a0 += xv.x*va.x + xv.y*va.y + xv.z*va.z + xv.w*va.w;
        a1 += xv.x*vb.x + xv.y*vb.y + xv.z*vb.z + xv.w*vb.w;
    }
    v0 = fmaxf(a0 + benc[lane], 0.f);
    v1 = fmaxf(a1 + benc[lane + 32], 0.f);
    unsigned long long k0 = ((unsigned long long)__float_as_uint(v0) << 32) | (unsigned)(63 - lane);
    unsigned long long k1 = ((unsigned long long)__float_as_uint(v1) << 32) | (unsigned)(31 - lane);
    float thx = 0.f;
    #pragma unroll
    for (int it = 0; it < KTOP; it++) {
        unsigned long long m = (k0 > k1) ? k0 : k1;
        #pragma unroll
        for (int off = 16; off > 0; off >>= 1) {
            unsigned long long o = __shfl_xor_sync(0xffffffffu, m, off);
            if (o > m) m = o;
        }
        if (it == KTOP - 1) thx = __uint_as_float((unsigned)(m >> 32));
        if (k0 == m) k0 = 0ull; else if (k1 == m) k1 = 0ull;
    }
    hr[lane]      = (v0 >= thx) ? v0 : 0.f;
    hr[lane + 32] = (v1 >= thx) ? v1 : 0.f;
}

// ---------------- K3: decoder GEMM (3xTF32, mma.sync) + bias ----------------
// Grid (13, rowtiles): col-tile varies fastest so the 13 CTAs sharing one
// 256-row h stripe are wave-co-resident -> h read once from DRAM, rest L2.
__global__ __launch_bounds__(256, 2) void k_dec(const float* __restrict__ h,
        const float* __restrict__ bdec, float* __restrict__ xhat, int B) {
    __shared__ float ws[KCH_D][64][16];
    const int tid = threadIdx.x, lane = tid & 31, w = tid >> 5;
    const int g = lane >> 2, tg = lane & 3;
    const int r0 = blockIdx.y * 256;
    const int n0 = blockIdx.x * 64;
    const int rowb = r0 + w * 32 + g;
    const float* hp[4];
    #pragma unroll
    for (int j = 0; j < 4; j++) {
        int r = min(rowb + 8 * j, B - 1);
        hp[j] = h + (size_t)r * HIDN + 2 * tg;
    }

    #pragma unroll
    for (int i = 0; i < 8; i++) {
        int f = tid + i * 256;
        int kc = f >> 8, q = f & 255, n = q >> 2, part = q & 3;
        cp16(&ws[kc][n][part * 4],
             g_Bd + ((size_t)kc * NPAD + n0 + n) * 16 + part * 4);
    }
    CP_COMMIT();
    CP_WAIT0();
    __syncthreads();

    float acc[8][8];
    #pragma unroll
    for (int t = 0; t < 8; t++)
        #pragma unroll
        for (int i = 0; i < 8; i++) acc[t][i] = 0.f;

    #pragma unroll
    for (int kc = 0; kc < KCH_D; kc++) {
        float2 a0 = *(const float2*)(hp[0] + kc * 8);
        float2 a1 = *(const float2*)(hp[1] + kc * 8);
        float2 a2 = *(const float2*)(hp[2] + kc * 8);
        float2 a3 = *(const float2*)(hp[3] + kc * 8);
        unsigned ah0[4], al0[4], ah1[4], al1[4];
        splitm(a0.x, ah0[0], al0[0]); splitm(a1.x, ah0[1], al0[1]);
        splitm(a0.y, ah0[2], al0[2]); splitm(a1.y, ah0[3], al0[3]);
        splitm(a2.x, ah1[0], al1[0]); splitm(a3.x, ah1[1], al1[1]);
        splitm(a2.y, ah1[2], al1[2]); splitm(a3.y, ah1[3], al1[3]);
        #pragma unroll
        for (int t = 0; t < 8; t++) {
            float4 bv = *(const float4*)&ws[kc][t * 8 + g][4 * tg];
            mma3(acc[t],     ah0, al0, bv);
            mma3(acc[t] + 4, ah1, al1, bv);
        }
    }

    #pragma unroll
    for (int t = 0; t < 8; t++) {
        int col = n0 + t * 8 + 2 * tg;
        if (col < IN) {
            float2 bb = *(const float2*)(bdec + col);
            #pragma unroll
            for (int s = 0; s < 4; s++) {
                int r = rowb + 8 * s;
                if (r < B) {
                    float u0 = (s & 1) ? acc[t][(s >> 1) * 4 + 2] : acc[t][(s >> 1) * 4 + 0];
                    float u1 = (s & 1) ? acc[t][(s >> 1) * 4 + 3] : acc[t][(s >> 1) * 4 + 1];
                    float2 o = make_float2(u0 + bb.x, u1 + bb.y);
                    *(float2*)(xhat + (size_t)r * IN + col) = o;
                }
            }
        }
    }
}

extern "C" void kernel_launch(void* const* d_in, const int* in_sizes, int n_in,
                              void* d_out, int out_size) {
    const float* x    = (const float*)d_in[0];
    const float* We   = (const float*)d_in[1];
    const float* benc = (const float*)d_in[2];
    const float* Wd   = (const float*)d_in[3];
    const float* bdec = (const float*)d_in[4];
    int B = in_sizes[0] / IN;

    float* hout = (float*)d_out;                         // [B, 64]
    float* xhat = (float*)d_out + (size_t)B * HIDN;      // [B, 784]

    const int SMEM_ENC = 4 * 24576;                      // 98304 bytes
    cudaFuncSetAttribute(k_enc, cudaFuncAttributeMaxDynamicSharedMemorySize, SMEM_ENC);

    const int NPREP = KCH_E * 1024 + KCH_D * NPAD * 16;
    k_prep<<<(NPREP + 255) / 256, 256>>>(We, Wd);
    k_enc<<<(B + 255) / 256, 256, SMEM_ENC>>>(x, benc, hout, B);
    k_topk<<<(B + 7) / 8, 256>>>(x, We, benc, hout, B);
    k_dec<<<dim3(13, (B + 255) / 256), 256>>>(hout, bdec, xhat, B);
}

// round 14
// speedup vs baseline: 1.2504x; 1.1070x over previous
#include <cuda_runtime.h>
#include <cstdint>

#define IN 784
#define HIDN 64
#define KTOP 20
#define KCH_E 98              // 98 chunks of 8 k (784 = 98*8)
#define GRP 7                 // chunks per weight group
#define NGRP 14               // 98 / 7
#define KCH_D 8               // decoder k-chunks
#define NPAD 832
#define EPS_GAP 1e-4f

// Pre-split weights. Layout [kc][n][k*2+hl]: one thread's 4 B-scalars per mma
// tile = one float4 = (bh(2tg), bl(2tg), bh(2tg+1), bl(2tg+1)).
__device__ float g_Be[KCH_E * 1024];          // 100352 floats
__device__ float g_Bd[KCH_D * NPAD * 16];     // 106496 floats

// ---- tf32 helpers ----
__device__ __forceinline__ unsigned tf32r(float v) {
    unsigned r; asm("cvt.rna.tf32.f32 %0, %1;" : "=r"(r) : "f"(v)); return r;
}
// Fast split: tf32 HMMA reads only bits[31:13]; hi = mask, lo = raw residual.
__device__ __forceinline__ void splitm(float v, unsigned &hi, unsigned &lo) {
    unsigned b = __float_as_uint(v);
    hi = b & 0xFFFFE000u;
    lo = __float_as_uint(v - __uint_as_float(hi));
}
__device__ __forceinline__ void mma8(float* c, const unsigned* a, unsigned b0, unsigned b1) {
    asm volatile(
        "mma.sync.aligned.m16n8k8.row.col.f32.tf32.tf32.f32 "
        "{%0,%1,%2,%3},{%4,%5,%6,%7},{%8,%9},{%0,%1,%2,%3};"
        : "+f"(c[0]), "+f"(c[1]), "+f"(c[2]), "+f"(c[3])
        : "r"(a[0]), "r"(a[1]), "r"(a[2]), "r"(a[3]), "r"(b0), "r"(b1));
}
__device__ __forceinline__ void mma3(float* c, const unsigned* ah, const unsigned* al, float4 bv) {
    unsigned bh0 = __float_as_uint(bv.x), bl0 = __float_as_uint(bv.y);
    unsigned bh1 = __float_as_uint(bv.z), bl1 = __float_as_uint(bv.w);
    mma8(c, ah, bh0, bh1);
    mma8(c, al, bh0, bh1);
    mma8(c, ah, bl0, bl1);
}
// ---- cp.async ----
__device__ __forceinline__ void cp16(void* sdst, const void* gsrc) {
    unsigned sa = (unsigned)__cvta_generic_to_shared(sdst);
    asm volatile("cp.async.ca.shared.global [%0], [%1], 16;" :: "r"(sa), "l"(gsrc));
}
#define CP_COMMIT() asm volatile("cp.async.commit_group;")
#define CP_WAIT0()  asm volatile("cp.async.wait_group 0;" ::: "memory")

// ---------------- K0: split + rearrange weights ----------------
__global__ void k_prep(const float* __restrict__ We, const float* __restrict__ Wd) {
    int idx = blockIdx.x * 256 + threadIdx.x;
    const int NE = KCH_E * 1024;
    if (idx < NE) {
        int kc = idx >> 10, r = idx & 1023;
        int n = r >> 4, q = r & 15, kk = q >> 1, hl = q & 1;
        float w = We[n * IN + kc * 8 + kk];
        unsigned h = tf32r(w);
        g_Be[idx] = hl ? __uint_as_float(tf32r(w - __uint_as_float(h)))
                       : __uint_as_float(h);
    }
    int j = idx - NE;
    const int ND = KCH_D * NPAD * 16;
    if (j >= 0 && j < ND) {
        int kc = j / (NPAD * 16);
        int r  = j % (NPAD * 16);
        int n = r >> 4, q = r & 15, kk = q >> 1, hl = q & 1;
        float w = (n < IN) ? Wd[n * HIDN + kc * 8 + kk] : 0.f;
        unsigned h = tf32r(w);
        g_Bd[j] = hl ? __uint_as_float(tf32r(w - __uint_as_float(h)))
                     : __uint_as_float(h);
    }
}

// ---------------- K1: encoder GEMM (3xTF32) + bias + ReLU ----------------
// Decoder-style: x (A operand) read DIRECTLY from global (no smem staging --
// zero intra-CTA reuse makes staging pure overhead); weights paged in groups
// of 7 chunks (28KB, 2 slots), ONE barrier per group (14 total). Prefetch of
// group g+1 flies while group g computes.
// CTA = 256 rows x 64 cols, 8 warps, warp = 32 rows (two A frags).
__global__ __launch_bounds__(256, 2) void k_enc(const float* __restrict__ x,
        const float* __restrict__ benc, float* __restrict__ hout, int B) {
    extern __shared__ char dyn[];                 // 2 x 28672 B weight slots
    const int tid = threadIdx.x, lane = tid & 31, w = tid >> 5;
    const int g = lane >> 2, tg = lane & 3;
    const int r0 = blockIdx.x * 256;
    const int rowb = r0 + w * 32 + g;
    const float* xp[4];
    #pragma unroll
    for (int j = 0; j < 4; j++) {
        int r = min(rowb + 8 * j, B - 1);
        xp[j] = x + (size_t)r * IN + 2 * tg;
    }

    float acc[8][8];
    #pragma unroll
    for (int t = 0; t < 8; t++)
        #pragma unroll
        for (int i = 0; i < 8; i++) acc[t][i] = 0.f;

    // prologue: group 0 (7 chunks x 1024 floats = 1792 float4, 7 per thread)
    #pragma unroll
    for (int i = 0; i < GRP; i++) {
        int f = tid + i * 256;
        cp16(dyn + f * 16, g_Be + f * 4);
    }
    CP_COMMIT();

    for (int gr = 0; gr < NGRP; gr++) {
        CP_WAIT0();               // group gr landed (issued a full group ago)
        __syncthreads();          // all threads' data visible; prev compute done

        if (gr + 1 < NGRP) {      // prefetch group gr+1 into the other slot
            char* sb = dyn + ((gr + 1) & 1) * 28672;
            const float* src = g_Be + (gr + 1) * (GRP * 1024);
            #pragma unroll
            for (int i = 0; i < GRP; i++) {
                int f = tid + i * 256;
                cp16(sb + f * 16, src + f * 4);
            }
            CP_COMMIT();
        }

        const float* wsb = (const float*)(dyn + (gr & 1) * 28672);
        #pragma unroll
        for (int lc = 0; lc < GRP; lc++) {
            const int kc = gr * GRP + lc;
            const float* wsp = wsb + lc * 1024;
            float2 a0 = *(const float2*)(xp[0] + kc * 8);
            float2 a1 = *(const float2*)(xp[1] + kc * 8);
            float2 a2 = *(const float2*)(xp[2] + kc * 8);
            float2 a3 = *(const float2*)(xp[3] + kc * 8);
            unsigned ah0[4], al0[4], ah1[4], al1[4];
            splitm(a0.x, ah0[0], al0[0]); splitm(a1.x, ah0[1], al0[1]);
            splitm(a0.y, ah0[2], al0[2]); splitm(a1.y, ah0[3], al0[3]);
            splitm(a2.x, ah1[0], al1[0]); splitm(a3.x, ah1[1], al1[1]);
            splitm(a2.y, ah1[2], al1[2]); splitm(a3.y, ah1[3], al1[3]);
            #pragma unroll
            for (int t = 0; t < 8; t++) {
                float4 bv = *(const float4*)(wsp + (t * 8 + g) * 16 + 4 * tg);
                mma3(acc[t],     ah0, al0, bv);
                mma3(acc[t] + 4, ah1, al1, bv);
            }
        }
    }

    #pragma unroll
    for (int t = 0; t < 8; t++) {
        int col = t * 8 + 2 * tg;
        float2 bb = *(const float2*)(benc + col);
        #pragma unroll
        for (int s = 0; s < 4; s++) {
            int r = rowb + 8 * s;
            if (r < B) {
                float u0 = (s & 1) ? acc[t][(s >> 1) * 4 + 2] : acc[t][(s >> 1) * 4 + 0];
                float u1 = (s & 1) ? acc[t][(s >> 1) * 4 + 3] : acc[t][(s >> 1) * 4 + 1];
                float2 o = make_float2(fmaxf(u0 + bb.x, 0.f), fmaxf(u1 + bb.y, 0.f));
                *(float2*)(hout + (size_t)r * HIDN + col) = o;
            }
        }
    }
}

// ---------------- K2: top-20 gating (32-bit keys) + inline exact repair -----
__global__ __launch_bounds__(256) void k_topk(const float* __restrict__ x,
        const float* __restrict__ We, const float* __restrict__ benc,
        float* __restrict__ h, int B) {
    int warp = threadIdx.x >> 5, lane = threadIdx.x & 31;
    int row = blockIdx.x * 8 + warp;
    if (row >= B) return;
    float* hr = h + (size_t)row * HIDN;
    float v0 = hr[lane], v1 = hr[lane + 32];

    unsigned q0 = (__float_as_uint(v0) & ~63u) | (unsigned)(63 - lane);
    unsigned q1 = (__float_as_uint(v1) & ~63u) | (unsigned)(31 - lane);
    float thr = 0.f, nxt = 0.f;
    #pragma unroll
    for (int it = 0; it < KTOP + 1; it++) {
        unsigned m = (q0 > q1) ? q0 : q1;
        #pragma unroll
        for (int off = 16; off > 0; off >>= 1) {
            unsigned o = __shfl_xor_sync(0xffffffffu, m, off);
            if (o > m) m = o;
        }
        if (it == KTOP - 1) thr = __uint_as_float(m & ~63u);
        if (it == KTOP)     nxt = __uint_as_float(m & ~63u);
        if (q0 == m) q0 = 0u; else if (q1 == m) q1 = 0u;
    }

    if (thr - nxt >= EPS_GAP) {
        hr[lane]      = (v0 >= thr) ? v0 : 0.f;
        hr[lane + 32] = (v1 >= thr) ? v1 : 0.f;
        return;
    }

    // Fragile: exact fp32 recompute + exact 64-bit-key top-k.
    const float* xr = x + (size_t)row * IN;
    const float* wa = We + (size_t)lane * IN;
    const float* wb = We + (size_t)(lane + 32) * IN;
    float a0 = 0.f, a1 = 0.f;
    for (int k = 0; k < IN; k += 4) {
        float4 xv = *(const float4*)(xr + k);
        float4 va = *(const float4*)(wa + k);
        float4 vb = *(const float4*)(wb + k);
        a0 += xv.x*va.x + xv.y*va.y + xv.z*va.z + xv.w*va.w;
        a1 += xv.x*vb.x + xv.y*vb.y + xv.z*vb.z + xv.w*vb.w;
    }
    v0 = fmaxf(a0 + benc[lane], 0.f);
    v1 = fmaxf(a1 + benc[lane + 32], 0.f);
    unsigned long long k0 = ((unsigned long long)__float_as_uint(v0) << 32) | (unsigned)(63 - lane);
    unsigned long long k1 = ((unsigned long long)__float_as_uint(v1) << 32) | (unsigned)(31 - lane);
    float thx = 0.f;
    #pragma unroll
    for (int it = 0; it < KTOP; it++) {
        unsigned long long m = (k0 > k1) ? k0 : k1;
        #pragma unroll
        for (int off = 16; off > 0; off >>= 1) {
            unsigned long long o = __shfl_xor_sync(0xffffffffu, m, off);
            if (o > m) m = o;
        }
        if (it == KTOP - 1) thx = __uint_as_float((unsigned)(m >> 32));
        if (k0 == m) k0 = 0ull; else if (k1 == m) k1 = 0ull;
    }
    hr[lane]      = (v0 >= thx) ? v0 : 0.f;
    hr[lane + 32] = (v1 >= thx) ? v1 : 0.f;
}

// ---------------- K3: decoder GEMM (3xTF32, mma.sync) + bias ----------------
// Grid (13, rowtiles): col-tile fastest -> 13 CTAs of a row stripe co-resident,
// h read once from DRAM, rest L2.
__global__ __launch_bounds__(256, 2) void k_dec(const float* __restrict__ h,
        const float* __restrict__ bdec, float* __restrict__ xhat, int B) {
    __shared__ float ws[KCH_D][64][16];
    const int tid = threadIdx.x, lane = tid & 31, w = tid >> 5;
    const int g = lane >> 2, tg = lane & 3;
    const int r0 = blockIdx.y * 256;
    const int n0 = blockIdx.x * 64;
    const int rowb = r0 + w * 32 + g;
    const float* hp[4];
    #pragma unroll
    for (int j = 0; j < 4; j++) {
        int r = min(rowb + 8 * j, B - 1);
        hp[j] = h + (size_t)r * HIDN + 2 * tg;
    }

    #pragma unroll
    for (int i = 0; i < 8; i++) {
        int f = tid + i * 256;
        int kc = f >> 8, q = f & 255, n = q >> 2, part = q & 3;
        cp16(&ws[kc][n][part * 4],
             g_Bd + ((size_t)kc * NPAD + n0 + n) * 16 + part * 4);
    }
    CP_COMMIT();
    CP_WAIT0();
    __syncthreads();

    float acc[8][8];
    #pragma unroll
    for (int t = 0; t < 8; t++)
        #pragma unroll
        for (int i = 0; i < 8; i++) acc[t][i] = 0.f;

    #pragma unroll
    for (int kc = 0; kc < KCH_D; kc++) {
        float2 a0 = *(const float2*)(hp[0] + kc * 8);
        float2 a1 = *(const float2*)(hp[1] + kc * 8);
        float2 a2 = *(const float2*)(hp[2] + kc * 8);
        float2 a3 = *(const float2*)(hp[3] + kc * 8);
        unsigned ah0[4], al0[4], ah1[4], al1[4];
        splitm(a0.x, ah0[0], al0[0]); splitm(a1.x, ah0[1], al0[1]);
        splitm(a0.y, ah0[2], al0[2]); splitm(a1.y, ah0[3], al0[3]);
        splitm(a2.x, ah1[0], al1[0]); splitm(a3.x, ah1[1], al1[1]);
        splitm(a2.y, ah1[2], al1[2]); splitm(a3.y, ah1[3], al1[3]);
        #pragma unroll
        for (int t = 0; t < 8; t++) {
            float4 bv = *(const float4*)&ws[kc][t * 8 + g][4 * tg];
            mma3(acc[t],     ah0, al0, bv);
            mma3(acc[t] + 4, ah1, al1, bv);
        }
    }

    #pragma unroll
    for (int t = 0; t < 8; t++) {
        int col = n0 + t * 8 + 2 * tg;
        if (col < IN) {
            float2 bb = *(const float2*)(bdec + col);
            #pragma unroll
            for (int s = 0; s < 4; s++) {
                int r = rowb + 8 * s;
                if (r < B) {
                    float u0 = (s & 1) ? acc[t][(s >> 1) * 4 + 2] : acc[t][(s >> 1) * 4 + 0];
                    float u1 = (s & 1) ? acc[t][(s >> 1) * 4 + 3] : acc[t][(s >> 1) * 4 + 1];
                    float2 o = make_float2(u0 + bb.x, u1 + bb.y);
                    *(float2*)(xhat + (size_t)r * IN + col) = o;
                }
            }
        }
    }
}

extern "C" void kernel_launch(void* const* d_in, const int* in_sizes, int n_in,
                              void* d_out, int out_size) {
    const float* x    = (const float*)d_in[0];
    const float* We   = (const float*)d_in[1];
    const float* benc = (const float*)d_in[2];
    const float* Wd   = (const float*)d_in[3];
    const float* bdec = (const float*)d_in[4];
    int B = in_sizes[0] / IN;

    float* hout = (float*)d_out;                         // [B, 64]
    float* xhat = (float*)d_out + (size_t)B * HIDN;      // [B, 784]

    const int SMEM_ENC = 2 * 28672;                      // 57344 bytes
    cudaFuncSetAttribute(k_enc, cudaFuncAttributeMaxDynamicSharedMemorySize, SMEM_ENC);

    const int NPREP = KCH_E * 1024 + KCH_D * NPAD * 16;
    k_prep<<<(NPREP + 255) / 256, 256>>>(We, Wd);
    k_enc<<<(B + 255) / 256, 256, SMEM_ENC>>>(x, benc, hout, B);
    k_topk<<<(B + 7) / 8, 256>>>(x, We, benc, hout, B);
    k_dec<<<dim3(13, (B + 255) / 256), 256>>>(hout, bdec, xhat, B);
}

// round 15
// speedup vs baseline: 1.7199x; 1.3755x over previous
#include <cuda_runtime.h>
#include <cuda_fp16.h>
#include <cstdint>

#define IN 784
#define HIDN 64
#define KTOP 20
#define NCH 49                // 49 chunks of 16 k (784 = 49*16)
#define GRP 7                 // chunks per weight group
#define NGRP 7                // 49 / 7
#define KCH_D 4               // decoder k16-chunks (64 = 4*16)
#define NPAD 832
#define EPS_GAP 1e-4f

// Pre-split fp16 weights in B-fragment layout. Per (k16-chunk, n, tg) one
// uint4 = (bh0, bh1, bl0, bl1): bh0 = f16x2(W[n][k0],W[n][k0+1]) with
// k0 = kc*16+2tg, bh1 at k0+8; bl* = f16x2 of the fp32 residuals.
__device__ uint4 g_Be[NCH * 64 * 4];          // 12544 uint4 = 200 KB
__device__ uint4 g_Bd[KCH_D * NPAD * 4];      // 13312 uint4 = 212 KB

// ---- fp16 split helpers ----
__device__ __forceinline__ void spl16(float a, float b, unsigned &hi, unsigned &lo) {
    __half2 h = __floats2half2_rn(a, b);              // .x=a (low), .y=b (high)
    float ra = a - __low2float(h);
    float rb = b - __high2float(h);
    __half2 l = __floats2half2_rn(ra, rb);
    hi = reinterpret_cast<unsigned&>(h);
    lo = reinterpret_cast<unsigned&>(l);
}
__device__ __forceinline__ void mmaf16(float* c, const unsigned* a, unsigned b0, unsigned b1) {
    asm volatile(
        "mma.sync.aligned.m16n8k16.row.col.f32.f16.f16.f32 "
        "{%0,%1,%2,%3},{%4,%5,%6,%7},{%8,%9},{%0,%1,%2,%3};"
        : "+f"(c[0]), "+f"(c[1]), "+f"(c[2]), "+f"(c[3])
        : "r"(a[0]), "r"(a[1]), "r"(a[2]), "r"(a[3]), "r"(b0), "r"(b1));
}
// 3-term fp16 product-sum: ah*bh + al*bh + ah*bl (missing al*bl ~ 2^-22 rel)
__device__ __forceinline__ void mma3h(float* c, const unsigned* ah, const unsigned* al, uint4 bv) {
    mmaf16(c, ah, bv.x, bv.y);
    mmaf16(c, al, bv.x, bv.y);
    mmaf16(c, ah, bv.z, bv.w);
}
// ---- cp.async ----
__device__ __forceinline__ void cp16(void* sdst, const void* gsrc) {
    unsigned sa = (unsigned)__cvta_generic_to_shared(sdst);
    asm volatile("cp.async.ca.shared.global [%0], [%1], 16;" :: "r"(sa), "l"(gsrc));
}
#define CP_COMMIT() asm volatile("cp.async.commit_group;")
#define CP_WAIT0()  asm volatile("cp.async.wait_group 0;" ::: "memory")

// ---------------- K0: split weights to fp16 hi/lo fragment layout ----------
__global__ void k_prep(const float* __restrict__ We, const float* __restrict__ Wd) {
    int idx = blockIdx.x * 256 + threadIdx.x;
    const int NE = NCH * 64 * 4;                  // 12544
    if (idx < NE) {
        int kc = idx >> 8, r = idx & 255, n = r >> 2, tg = r & 3;
        int k0 = kc * 16 + 2 * tg;
        float w0 = We[n * IN + k0],     w1 = We[n * IN + k0 + 1];
        float w2 = We[n * IN + k0 + 8], w3 = We[n * IN + k0 + 9];
        uint4 v;
        spl16(w0, w1, v.x, v.z);
        spl16(w2, w3, v.y, v.w);
        g_Be[idx] = v;
    }
    int j = idx - NE;
    const int ND = KCH_D * NPAD * 4;              // 13312
    if (j >= 0 && j < ND) {
        int kc = j / (NPAD * 4), r = j % (NPAD * 4), n = r >> 2, tg = r & 3;
        int k0 = kc * 16 + 2 * tg;
        float w0 = 0.f, w1 = 0.f, w2 = 0.f, w3 = 0.f;
        if (n < IN) {
            w0 = Wd[n * HIDN + k0];     w1 = Wd[n * HIDN + k0 + 1];
            w2 = Wd[n * HIDN + k0 + 8]; w3 = Wd[n * HIDN + k0 + 9];
        }
        uint4 v;
        spl16(w0, w1, v.x, v.z);
        spl16(w2, w3, v.y, v.w);
        g_Bd[j] = v;
    }
}

// ---------------- K1: encoder GEMM (3xFP16 m16n8k16) + bias + ReLU ---------
// CTA = 256 rows x 64 cols, 8 warps, warp = 32 rows (two A frags).
// x read directly from global; weights paged in groups of 7 k16-chunks
// (28KB, 2 slots), one barrier per group (7 total).
__global__ __launch_bounds__(256, 2) void k_enc(const float* __restrict__ x,
        const float* __restrict__ benc, float* __restrict__ hout, int B) {
    extern __shared__ char dyn[];                 // 2 x 28672 B weight slots
    const int tid = threadIdx.x, lane = tid & 31, w = tid >> 5;
    const int g = lane >> 2, tg = lane & 3;
    const int r0 = blockIdx.x * 256;
    const int rowb = r0 + w * 32 + g;
    const float* xp[4];
    #pragma unroll
    for (int j = 0; j < 4; j++) {
        int r = min(rowb + 8 * j, B - 1);
        xp[j] = x + (size_t)r * IN + 2 * tg;
    }

    float acc[8][8];
    #pragma unroll
    for (int t = 0; t < 8; t++)
        #pragma unroll
        for (int i = 0; i < 8; i++) acc[t][i] = 0.f;

    // prologue: group 0 (7 chunks x 256 uint4 = 1792 uint4, 7 per thread)
    #pragma unroll
    for (int i = 0; i < GRP; i++) {
        int f = tid + i * 256;
        cp16(dyn + f * 16, (const char*)g_Be + f * 16);
    }
    CP_COMMIT();

    for (int gr = 0; gr < NGRP; gr++) {
        CP_WAIT0();
        __syncthreads();

        if (gr + 1 < NGRP) {
            char* sb = dyn + ((gr + 1) & 1) * 28672;
            const char* src = (const char*)g_Be + (gr + 1) * 28672;
            #pragma unroll
            for (int i = 0; i < GRP; i++) {
                int f = tid + i * 256;
                cp16(sb + f * 16, src + f * 16);
            }
            CP_COMMIT();
        }

        const char* wsb = dyn + (gr & 1) * 28672;
        #pragma unroll
        for (int lc = 0; lc < GRP; lc++) {
            const int kc = gr * GRP + lc;
            const uint4* wsp = (const uint4*)(wsb + lc * 4096);
            unsigned ah0[4], al0[4], ah1[4], al1[4];
            #pragma unroll
            for (int j = 0; j < 4; j++) {
                float2 pA = *(const float2*)(xp[j] + kc * 16);
                float2 pB = *(const float2*)(xp[j] + kc * 16 + 8);
                unsigned hA, lA, hB, lB;
                spl16(pA.x, pA.y, hA, lA);
                spl16(pB.x, pB.y, hB, lB);
                if (j < 2) { ah0[j] = hA; ah0[j + 2] = hB; al0[j] = lA; al0[j + 2] = lB; }
                else       { ah1[j - 2] = hA; ah1[j] = hB; al1[j - 2] = lA; al1[j] = lB; }
            }
            #pragma unroll
            for (int t = 0; t < 8; t++) {
                uint4 bv = wsp[(t * 8 + g) * 4 + tg];
                mma3h(acc[t],     ah0, al0, bv);
                mma3h(acc[t] + 4, ah1, al1, bv);
            }
        }
    }

    #pragma unroll
    for (int t = 0; t < 8; t++) {
        int col = t * 8 + 2 * tg;
        float2 bb = *(const float2*)(benc + col);
        #pragma unroll
        for (int s = 0; s < 4; s++) {
            int r = rowb + 8 * s;
            if (r < B) {
                float u0 = (s & 1) ? acc[t][(s >> 1) * 4 + 2] : acc[t][(s >> 1) * 4 + 0];
                float u1 = (s & 1) ? acc[t][(s >> 1) * 4 + 3] : acc[t][(s >> 1) * 4 + 1];
                float2 o = make_float2(fmaxf(u0 + bb.x, 0.f), fmaxf(u1 + bb.y, 0.f));
                *(float2*)(hout + (size_t)r * HIDN + col) = o;
            }
        }
    }
}

// ---------------- K2: top-20 gating (32-bit keys) + inline exact repair -----
__global__ __launch_bounds__(256) void k_topk(const float* __restrict__ x,
        const float* __restrict__ We, const float* __restrict__ benc,
        float* __restrict__ h, int B) {
    int warp = threadIdx.x >> 5, lane = threadIdx.x & 31;
    int row = blockIdx.x * 8 + warp;
    if (row >= B) return;
    float* hr = h + (size_t)row * HIDN;
    float v0 = hr[lane], v1 = hr[lane + 32];

    unsigned q0 = (__float_as_uint(v0) & ~63u) | (unsigned)(63 - lane);
    unsigned q1 = (__float_as_uint(v1) & ~63u) | (unsigned)(31 - lane);
    float thr = 0.f, nxt = 0.f;
    #pragma unroll
    for (int it = 0; it < KTOP + 1; it++) {
        unsigned m = (q0 > q1) ? q0 : q1;
        #pragma unroll
        for (int off = 16; off > 0; off >>= 1) {
            unsigned o = __shfl_xor_sync(0xffffffffu, m, off);
            if (o > m) m = o;
        }
        if (it == KTOP - 1) thr = __uint_as_float(m & ~63u);
        if (it == KTOP)     nxt = __uint_as_float(m & ~63u);
        if (q0 == m) q0 = 0u; else if (q1 == m) q1 = 0u;
    }

    if (thr - nxt >= EPS_GAP) {
        hr[lane]      = (v0 >= thr) ? v0 : 0.f;
        hr[lane + 32] = (v1 >= thr) ? v1 : 0.f;
        return;
    }

    // Fragile: exact fp32 recompute + exact 64-bit-key top-k.
    const float* xr = x + (size_t)row * IN;
    const float* wa = We + (size_t)lane * IN;
    const float* wb = We + (size_t)(lane + 32) * IN;
    float a0 = 0.f, a1 = 0.f;
    for (int k = 0; k < IN; k += 4) {
        float4 xv = *(const float4*)(xr + k);
        float4 va = *(const float4*)(wa + k);
        float4 vb = *(const float4*)(wb + k);
        a0 += xv.x*va.x + xv.y*va.y + xv.z*va.z + xv.w*va.w;
        a1 += xv.x*vb.x + xv.y*vb.y + xv.z*vb.z + xv.w*vb.w;
    }
    v0 = fmaxf(a0 + benc[lane], 0.f);
    v1 = fmaxf(a1 + benc[lane + 32], 0.f);
    unsigned long long k0 = ((unsigned long long)__float_as_uint(v0) << 32) | (unsigned)(63 - lane);
    unsigned long long k1 = ((unsigned long long)__float_as_uint(v1) << 32) | (unsigned)(31 - lane);
    float thx = 0.f;
    #pragma unroll
    for (int it = 0; it < KTOP; it++) {
        unsigned long long m = (k0 > k1) ? k0 : k1;
        #pragma unroll
        for (int off = 16; off > 0; off >>= 1) {
            unsigned long long o = __shfl_xor_sync(0xffffffffu, m, off);
            if (o > m) m = o;
        }
        if (it == KTOP - 1) thx = __uint_as_float((unsigned)(m >> 32));
        if (k0 == m) k0 = 0ull; else if (k1 == m) k1 = 0ull;
    }
    hr[lane]      = (v0 >= thx) ? v0 : 0.f;
    hr[lane + 32] = (v1 >= thx) ? v1 : 0.f;
}

// ---------------- K3: decoder GEMM (3xFP16 m16n8k16) + bias ----------------
// Grid (13, rowtiles): col-tile fastest -> h stripe L2-resident across the 13
// co-scheduled CTAs. K = 64 = 4 k16-chunks, B staged once (16 KB).
__global__ __launch_bounds__(256, 2) void k_dec(const float* __restrict__ h,
        const float* __restrict__ bdec, float* __restrict__ xhat, int B) {
    __shared__ uint4 ws4[KCH_D * 256];            // 16 KB
    const int tid = threadIdx.x, lane = tid & 31, w = tid >> 5;
    const int g = lane >> 2, tg = lane & 3;
    const int r0 = blockIdx.y * 256;
    const int n0 = blockIdx.x * 64;
    const int rowb = r0 + w * 32 + g;
    const float* hp[4];
    #pragma unroll
    for (int j = 0; j < 4; j++) {
        int r = min(rowb + 8 * j, B - 1);
        hp[j] = h + (size_t)r * HIDN + 2 * tg;
    }

    // stage B: 4 chunks x 256 uint4 = 1024 uint4 / 256 thr = 4 per thread
    #pragma unroll
    for (int i = 0; i < 4; i++) {
        int f = tid + i * 256;
        int kc = f >> 8, r = f & 255, n = r >> 2, tgq = r & 3;
        cp16(&ws4[f], g_Bd + (size_t)(kc * NPAD + n0 + n) * 4 + tgq);
    }
    CP_COMMIT();
    CP_WAIT0();
    __syncthreads();

    float acc[8][8];
    #pragma unroll
    for (int t = 0; t < 8; t++)
        #pragma unroll
        for (int i = 0; i < 8; i++) acc[t][i] = 0.f;

    #pragma unroll
    for (int kc = 0; kc < KCH_D; kc++) {
        unsigned ah0[4], al0[4], ah1[4], al1[4];
        #pragma unroll
        for (int j = 0; j < 4; j++) {
            float2 pA = *(const float2*)(hp[j] + kc * 16);
            float2 pB = *(const float2*)(hp[j] + kc * 16 + 8);
            unsigned hA, lA, hB, lB;
            spl16(pA.x, pA.y, hA, lA);
            spl16(pB.x, pB.y, hB, lB);
            if (j < 2) { ah0[j] = hA; ah0[j + 2] = hB; al0[j] = lA; al0[j + 2] = lB; }
            else       { ah1[j - 2] = hA; ah1[j] = hB; al1[j - 2] = lA; al1[j] = lB; }
        }
        #pragma unroll
        for (int t = 0; t < 8; t++) {
            uint4 bv = ws4[kc * 256 + (t * 8 + g) * 4 + tg];
            mma3h(acc[t],     ah0, al0, bv);
            mma3h(acc[t] + 4, ah1, al1, bv);
        }
    }

    #pragma unroll
    for (int t = 0; t < 8; t++) {
        int col = n0 + t * 8 + 2 * tg;
        if (col < IN) {
            float2 bb = *(const float2*)(bdec + col);
            #pragma unroll
            for (int s = 0; s < 4; s++) {
                int r = rowb + 8 * s;
                if (r < B) {
                    float u0 = (s & 1) ? acc[t][(s >> 1) * 4 + 2] : acc[t][(s >> 1) * 4 + 0];
                    float u1 = (s & 1) ? acc[t][(s >> 1) * 4 + 3] : acc[t][(s >> 1) * 4 + 1];
                    float2 o = make_float2(u0 + bb.x, u1 + bb.y);
                    *(float2*)(xhat + (size_t)r * IN + col) = o;
                }
            }
        }
    }
}

extern "C" void kernel_launch(void* const* d_in, const int* in_sizes, int n_in,
                              void* d_out, int out_size) {
    const float* x    = (const float*)d_in[0];
    const float* We   = (const float*)d_in[1];
    const float* benc = (const float*)d_in[2];
    const float* Wd   = (const float*)d_in[3];
    const float* bdec = (const float*)d_in[4];
    int B = in_sizes[0] / IN;

    float* hout = (float*)d_out;                         // [B, 64]
    float* xhat = (float*)d_out + (size_t)B * HIDN;      // [B, 784]

    const int SMEM_ENC = 2 * 28672;                      // 57344 bytes
    cudaFuncSetAttribute(k_enc, cudaFuncAttributeMaxDynamicSharedMemorySize, SMEM_ENC);

    const int NPREP = NCH * 64 * 4 + KCH_D * NPAD * 4;   // 25856 threads
    k_prep<<<(NPREP + 255) / 256, 256>>>(We, Wd);
    k_enc<<<(B + 255) / 256, 256, SMEM_ENC>>>(x, benc, hout, B);
    k_topk<<<(B + 7) / 8, 256>>>(x, We, benc, hout, B);
    k_dec<<<dim3(13, (B + 255) / 256), 256>>>(hout, bdec, xhat, B);
}

// round 16
// speedup vs baseline: 1.7206x; 1.0004x over previous
#include <cuda_runtime.h>
#include <cuda_fp16.h>
#include <cstdint>

#define IN 784
#define HIDN 64
#define KTOP 20
#define NCH 49                // 49 chunks of 16 k (784 = 49*16)
#define GRP 7                 // chunks per weight group
#define NGRP 7                // 49 / 7
#define KCH_D 4               // decoder k16-chunks (64 = 4*16)
#define NPAD 832
#define EPS_GAP 1e-4f

// Pre-split fp16 weights in B-fragment layout. Per (k16-chunk, n, tg) one
// uint4 = (bh0, bh1, bl0, bl1): bh0 = f16x2(W[n][k0],W[n][k0+1]) with
// k0 = kc*16+2tg, bh1 at k0+8; bl* = f16x2 of the fp32 residuals.
__device__ uint4 g_Be[NCH * 64 * 4];          // 12544 uint4 = 200 KB
__device__ uint4 g_Bd[KCH_D * NPAD * 4];      // 13312 uint4 = 212 KB

// ---- fp16 split helpers ----
__device__ __forceinline__ void spl16(float a, float b, unsigned &hi, unsigned &lo) {
    __half2 h = __floats2half2_rn(a, b);              // .x=a (low), .y=b (high)
    float ra = a - __low2float(h);
    float rb = b - __high2float(h);
    __half2 l = __floats2half2_rn(ra, rb);
    hi = reinterpret_cast<unsigned&>(h);
    lo = reinterpret_cast<unsigned&>(l);
}
__device__ __forceinline__ void mmaf16(float* c, const unsigned* a, unsigned b0, unsigned b1) {
    asm volatile(
        "mma.sync.aligned.m16n8k16.row.col.f32.f16.f16.f32 "
        "{%0,%1,%2,%3},{%4,%5,%6,%7},{%8,%9},{%0,%1,%2,%3};"
        : "+f"(c[0]), "+f"(c[1]), "+f"(c[2]), "+f"(c[3])
        : "r"(a[0]), "r"(a[1]), "r"(a[2]), "r"(a[3]), "r"(b0), "r"(b1));
}
// 3-term fp16 product-sum: ah*bh + al*bh + ah*bl (missing al*bl ~ 2^-22 rel)
__device__ __forceinline__ void mma3h(float* c, const unsigned* ah, const unsigned* al, uint4 bv) {
    mmaf16(c, ah, bv.x, bv.y);
    mmaf16(c, al, bv.x, bv.y);
    mmaf16(c, ah, bv.z, bv.w);
}
// ---- cp.async ----
__device__ __forceinline__ void cp16(void* sdst, const void* gsrc) {
    unsigned sa = (unsigned)__cvta_generic_to_shared(sdst);
    asm volatile("cp.async.ca.shared.global [%0], [%1], 16;" :: "r"(sa), "l"(gsrc));
}
#define CP_COMMIT() asm volatile("cp.async.commit_group;")
#define CP_WAIT0()  asm volatile("cp.async.wait_group 0;" ::: "memory")

// ---------------- K0: split weights to fp16 hi/lo fragment layout ----------
__global__ void k_prep(const float* __restrict__ We, const float* __restrict__ Wd) {
    int idx = blockIdx.x * 256 + threadIdx.x;
    const int NE = NCH * 64 * 4;                  // 12544
    if (idx < NE) {
        int kc = idx >> 8, r = idx & 255, n = r >> 2, tg = r & 3;
        int k0 = kc * 16 + 2 * tg;
        float w0 = We[n * IN + k0],     w1 = We[n * IN + k0 + 1];
        float w2 = We[n * IN + k0 + 8], w3 = We[n * IN + k0 + 9];
        uint4 v;
        spl16(w0, w1, v.x, v.z);
        spl16(w2, w3, v.y, v.w);
        g_Be[idx] = v;
    }
    int j = idx - NE;
    const int ND = KCH_D * NPAD * 4;              // 13312
    if (j >= 0 && j < ND) {
        int kc = j / (NPAD * 4), r = j % (NPAD * 4), n = r >> 2, tg = r & 3;
        int k0 = kc * 16 + 2 * tg;
        float w0 = 0.f, w1 = 0.f, w2 = 0.f, w3 = 0.f;
        if (n < IN) {
            w0 = Wd[n * HIDN + k0];     w1 = Wd[n * HIDN + k0 + 1];
            w2 = Wd[n * HIDN + k0 + 8]; w3 = Wd[n * HIDN + k0 + 9];
        }
        uint4 v;
        spl16(w0, w1, v.x, v.z);
        spl16(w2, w3, v.y, v.w);
        g_Bd[j] = v;
    }
}

// ---------------- K1: encoder GEMM (3xFP16 m16n8k16) + bias + ReLU ---------
// CTA = 256 rows x 64 cols, 8 warps, warp = 32 rows (two A frags).
// x read directly from global; weights paged in groups of 7 k16-chunks
// (28KB, 2 slots), one barrier per group (7 total).
__global__ __launch_bounds__(256, 2) void k_enc(const float* __restrict__ x,
        const float* __restrict__ benc, float* __restrict__ hout, int B) {
    extern __shared__ char dyn[];                 // 2 x 28672 B weight slots
    const int tid = threadIdx.x, lane = tid & 31, w = tid >> 5;
    const int g = lane >> 2, tg = lane & 3;
    const int r0 = blockIdx.x * 256;
    const int rowb = r0 + w * 32 + g;
    const float* xp[4];
    #pragma unroll
    for (int j = 0; j < 4; j++) {
        int r = min(rowb + 8 * j, B - 1);
        xp[j] = x + (size_t)r * IN + 2 * tg;
    }

    float acc[8][8];
    #pragma unroll
    for (int t = 0; t < 8; t++)
        #pragma unroll
        for (int i = 0; i < 8; i++) acc[t][i] = 0.f;

    // prologue: group 0 (7 chunks x 256 uint4 = 1792 uint4, 7 per thread)
    #pragma unroll
    for (int i = 0; i < GRP; i++) {
        int f = tid + i * 256;
        cp16(dyn + f * 16, (const char*)g_Be + f * 16);
    }
    CP_COMMIT();

    for (int gr = 0; gr < NGRP; gr++) {
        CP_WAIT0();
        __syncthreads();

        if (gr + 1 < NGRP) {
            char* sb = dyn + ((gr + 1) & 1) * 28672;
            const char* src = (const char*)g_Be + (gr + 1) * 28672;
            #pragma unroll
            for (int i = 0; i < GRP; i++) {
                int f = tid + i * 256;
                cp16(sb + f * 16, src + f * 16);
            }
            CP_COMMIT();
        }

        const char* wsb = dyn + (gr & 1) * 28672;
        #pragma unroll
        for (int lc = 0; lc < GRP; lc++) {
            const int kc = gr * GRP + lc;
            const uint4* wsp = (const uint4*)(wsb + lc * 4096);
            unsigned ah0[4], al0[4], ah1[4], al1[4];
            #pragma unroll
            for (int j = 0; j < 4; j++) {
                float2 pA = *(const float2*)(xp[j] + kc * 16);
                float2 pB = *(const float2*)(xp[j] + kc * 16 + 8);
                unsigned hA, lA, hB, lB;
                spl16(pA.x, pA.y, hA, lA);
                spl16(pB.x, pB.y, hB, lB);
                if (j < 2) { ah0[j] = hA; ah0[j + 2] = hB; al0[j] = lA; al0[j + 2] = lB; }
                else       { ah1[j - 2] = hA; ah1[j] = hB; al1[j - 2] = lA; al1[j] = lB; }
            }
            #pragma unroll
            for (int t = 0; t < 8; t++) {
                uint4 bv = wsp[(t * 8 + g) * 4 + tg];
                mma3h(acc[t],     ah0, al0, bv);
                mma3h(acc[t] + 4, ah1, al1, bv);
            }
        }
    }

    #pragma unroll
    for (int t = 0; t < 8; t++) {
        int col = t * 8 + 2 * tg;
        float2 bb = *(const float2*)(benc + col);
        #pragma unroll
        for (int s = 0; s < 4; s++) {
            int r = rowb + 8 * s;
            if (r < B) {
                float u0 = (s & 1) ? acc[t][(s >> 1) * 4 + 2] : acc[t][(s >> 1) * 4 + 0];
                float u1 = (s & 1) ? acc[t][(s >> 1) * 4 + 3] : acc[t][(s >> 1) * 4 + 1];
                float2 o = make_float2(fmaxf(u0 + bb.x, 0.f), fmaxf(u1 + bb.y, 0.f));
                *(float2*)(hout + (size_t)r * HIDN + col) = o;
            }
        }
    }
}

// ---------------- K2: top-20 gating (32-bit keys) + inline exact repair -----
__global__ __launch_bounds__(256) void k_topk(const float* __restrict__ x,
        const float* __restrict__ We, const float* __restrict__ benc,
        float* __restrict__ h, int B) {
    int warp = threadIdx.x >> 5, lane = threadIdx.x & 31;
    int row = blockIdx.x * 8 + warp;
    if (row >= B) return;
    float* hr = h + (size_t)row * HIDN;
    float v0 = hr[lane], v1 = hr[lane + 32];

    unsigned q0 = (__float_as_uint(v0) & ~63u) | (unsigned)(63 - lane);
    unsigned q1 = (__float_as_uint(v1) & ~63u) | (unsigned)(31 - lane);
    float thr = 0.f, nxt = 0.f;
    #pragma unroll
    for (int it = 0; it < KTOP + 1; it++) {
        unsigned m = (q0 > q1) ? q0 : q1;
        #pragma unroll
        for (int off = 16; off > 0; off >>= 1) {
            unsigned o = __shfl_xor_sync(0xffffffffu, m, off);
            if (o > m) m = o;
        }
        if (it == KTOP - 1) thr = __uint_as_float(m & ~63u);
        if (it == KTOP)     nxt = __uint_as_float(m & ~63u);
        if (q0 == m) q0 = 0u; else if (q1 == m) q1 = 0u;
    }

    if (thr - nxt >= EPS_GAP) {
        hr[lane]      = (v0 >= thr) ? v0 : 0.f;
        hr[lane + 32] = (v1 >= thr) ? v1 : 0.f;
        return;
    }

    // Fragile: exact fp32 recompute + exact 64-bit-key top-k.
    const float* xr = x + (size_t)row * IN;
    const float* wa = We + (size_t)lane * IN;
    const float* wb = We + (size_t)(lane + 32) * IN;
    float a0 = 0.f, a1 = 0.f;
    for (int k = 0; k < IN; k += 4) {
        float4 xv = *(const float4*)(xr + k);
        float4 va = *(const float4*)(wa + k);
        float4 vb = *(const float4*)(wb + k);
        a0 += xv.x*va.x + xv.y*va.y + xv.z*va.z + xv.w*va.w;
        a1 += xv.x*vb.x + xv.y*vb.y + xv.z*vb.z + xv.w*vb.w;
    }
    v0 = fmaxf(a0 + benc[lane], 0.f);
    v1 = fmaxf(a1 + benc[lane + 32], 0.f);
    unsigned long long k0 = ((unsigned long long)__float_as_uint(v0) << 32) | (unsigned)(63 - lane);
    unsigned long long k1 = ((unsigned long long)__float_as_uint(v1) << 32) | (unsigned)(31 - lane);
    float thx = 0.f;
    #pragma unroll
    for (int it = 0; it < KTOP; it++) {
        unsigned long long m = (k0 > k1) ? k0 : k1;
        #pragma unroll
        for (int off = 16; off > 0; off >>= 1) {
            unsigned long long o = __shfl_xor_sync(0xffffffffu, m, off);
            if (o > m) m = o;
        }
        if (it == KTOP - 1) thx = __uint_as_float((unsigned)(m >> 32));
        if (k0 == m) k0 = 0ull; else if (k1 == m) k1 = 0ull;
    }
    hr[lane]      = (v0 >= thx) ? v0 : 0.f;
    hr[lane + 32] = (v1 >= thx) ? v1 : 0.f;
}

// ---------------- K3: decoder GEMM (3xFP16 m16n8k16) + bias ----------------
// Grid (13, rowtiles): col-tile fastest -> h stripe L2-resident across the 13
// co-scheduled CTAs. K = 64 = 4 k16-chunks, B staged once (16 KB).
__global__ __launch_bounds__(256, 2) void k_dec(const float* __restrict__ h,
        const float* __restrict__ bdec, float* __restrict__ xhat, int B) {
    __shared__ uint4 ws4[KCH_D * 256];            // 16 KB
    const int tid = threadIdx.x, lane = tid & 31, w = tid >> 5;
    const int g = lane >> 2, tg = lane & 3;
    const int r0 = blockIdx.y * 256;
    const int n0 = blockIdx.x * 64;
    const int rowb = r0 + w * 32 + g;
    const float* hp[4];
    #pragma unroll
    for (int j = 0; j < 4; j++) {
        int r = min(rowb + 8 * j, B - 1);
        hp[j] = h + (size_t)r * HIDN + 2 * tg;
    }

    // stage B: 4 chunks x 256 uint4 = 1024 uint4 / 256 thr = 4 per thread
    #pragma unroll
    for (int i = 0; i < 4; i++) {
        int f = tid + i * 256;
        int kc = f >> 8, r = f & 255, n = r >> 2, tgq = r & 3;
        cp16(&ws4[f], g_Bd + (size_t)(kc * NPAD + n0 + n) * 4 + tgq);
    }
    CP_COMMIT();
    CP_WAIT0();
    __syncthreads();

    float acc[8][8];
    #pragma unroll
    for (int t = 0; t < 8; t++)
        #pragma unroll
        for (int i = 0; i < 8; i++) acc[t][i] = 0.f;

    #pragma unroll
    for (int kc = 0; kc < KCH_D; kc++) {
        unsigned ah0[4], al0[4], ah1[4], al1[4];
        #pragma unroll
        for (int j = 0; j < 4; j++) {
            float2 pA = *(const float2*)(hp[j] + kc * 16);
            float2 pB = *(const float2*)(hp[j] + kc * 16 + 8);
            unsigned hA, lA, hB, lB;
            spl16(pA.x, pA.y, hA, lA);
            spl16(pB.x, pB.y, hB, lB);
            if (j < 2) { ah0[j] = hA; ah0[j + 2] = hB; al0[j] = lA; al0[j + 2] = lB; }
            else       { ah1[j - 2] = hA; ah1[j] = hB; al1[j - 2] = lA; al1[j] = lB; }
        }
        #pragma unroll
        for (int t = 0; t < 8; t++) {
            uint4 bv = ws4[kc * 256 + (t * 8 + g) * 4 + tg];
            mma3h(acc[t],     ah0, al0, bv);
            mma3h(acc[t] + 4, ah1, al1, bv);
        }
    }

    #pragma unroll
    for (int t = 0; t < 8; t++) {
        int col = n0 + t * 8 + 2 * tg;
        if (col < IN) {
            float2 bb = *(const float2*)(bdec + col);
            #pragma unroll
            for (int s = 0; s < 4; s++) {
                int r = rowb + 8 * s;
                if (r < B) {
                    float u0 = (s & 1) ? acc[t][(s >> 1) * 4 + 2] : acc[t][(s >> 1) * 4 + 0];
                    float u1 = (s & 1) ? acc[t][(s >> 1) * 4 + 3] : acc[t][(s >> 1) * 4 + 1];
                    float2 o = make_float2(u0 + bb.x, u1 + bb.y);
                    *(float2*)(xhat + (size_t)r * IN + col) = o;
                }
            }
        }
    }
}

extern "C" void kernel_launch(void* const* d_in, const int* in_sizes, int n_in,
                              void* d_out, int out_size) {
    const float* x    = (const float*)d_in[0];
    const float* We   = (const float*)d_in[1];
    const float* benc = (const float*)d_in[2];
    const float* Wd   = (const float*)d_in[3];
    const float* bdec = (const float*)d_in[4];
    int B = in_sizes[0] / IN;

    float* hout = (float*)d_out;                         // [B, 64]
    float* xhat = (float*)d_out + (size_t)B * HIDN;      // [B, 784]

    const int SMEM_ENC = 2 * 28672;                      // 57344 bytes
    cudaFuncSetAttribute(k_enc, cudaFuncAttributeMaxDynamicSharedMemorySize, SMEM_ENC);

    const int NPREP = NCH * 64 * 4 + KCH_D * NPAD * 4;   // 25856 threads
    k_prep<<<(NPREP + 255) / 256, 256>>>(We, Wd);
    k_enc<<<(B + 255) / 256, 256, SMEM_ENC>>>(x, benc, hout, B);
    k_topk<<<(B + 7) / 8, 256>>>(x, We, benc, hout, B);
    k_dec<<<dim3(13, (B + 255) / 256), 256>>>(hout, bdec, xhat, B);
}